// round 12
// baseline (speedup 1.0000x reference)
#include <cuda_runtime.h>

// GACRF fused: softmax(C=19) -> encode(G=8) -> 3x3 dynamic filter -> decode ->
// logit - result.  Single kernel, 64x16 tile + 1px halo in smem.
//
// R11: phase-1 E broadcasts via PRE-DUPLICATED rows. L1tex (69%) is the lead
// unit and per-warp wavefront accounting shows the phase-1 per-(c,g) LDS.64
// E broadcast is ~1/3 of all wavefronts (304/warp). E is now stored in smem as
// [E0,E0,E1,E1,...,E7,E7] per channel, so 4 broadcast LDS.128 per channel
// replace 8 LDS.64 -- and each float4's .xy/.zw halves are directly valid
// (Eg,Eg) FFMA2 multipliers (aligned reg pairs, zero MOVs, zero layout change).
// Unlike R9, accumulators / stores / load batching are untouched.
//
// Shapes (fixed): b=4, C=19, G=8, H=W=512, K=3.

#define BATCH 4
#define NC 19
#define NG 8
#define IMH 512
#define IMW 512
#define HW (IMH * IMW)

#define TW 64            // output tile width
#define TH 16            // output tile height
#define EH (TH + 2)      // 18 extended rows (global y0-1 .. y0+16)
#define EWP 72           // padded extended width, covers global [x0-4, x0+68)
#define NPAIR (EH * 9)   // 162 phase-1 threads, each owns 2 adjacent 4-px groups
#define NTHREADS 256

// ---- packed f32x2 helpers (per-lane IEEE identical to scalar) ----
__device__ __forceinline__ float2 ffma2(float2 a, float2 b, float2 c) {
    float2 d;
    asm("fma.rn.f32x2 %0, %1, %2, %3;"
        : "=l"(*reinterpret_cast<unsigned long long*>(&d))
        : "l"(*reinterpret_cast<unsigned long long*>(&a)),
          "l"(*reinterpret_cast<unsigned long long*>(&b)),
          "l"(*reinterpret_cast<unsigned long long*>(&c)));
    return d;
}
__device__ __forceinline__ float2 fadd2(float2 a, float2 b) {
    float2 d;
    asm("add.rn.f32x2 %0, %1, %2;"
        : "=l"(*reinterpret_cast<unsigned long long*>(&d))
        : "l"(*reinterpret_cast<unsigned long long*>(&a)),
          "l"(*reinterpret_cast<unsigned long long*>(&b)));
    return d;
}
__device__ __forceinline__ float2 fmul2(float2 a, float2 b) {
    float2 d;
    asm("mul.rn.f32x2 %0, %1, %2;"
        : "=l"(*reinterpret_cast<unsigned long long*>(&d))
        : "l"(*reinterpret_cast<unsigned long long*>(&a)),
          "l"(*reinterpret_cast<unsigned long long*>(&b)));
    return d;
}

__global__ __launch_bounds__(NTHREADS, 3) void gacrf_fused_kernel(
    const float* __restrict__ Fk,     // [b,9,H,W]
    const float* __restrict__ logit,  // [b,C,H,W]
    const float* __restrict__ matrix, // [G,C]
    float* __restrict__ out)          // [b,C,H,W]
{
    __shared__ __align__(16) float EshDup[NC][2 * NG];  // [E0,E0,E1,E1,...], 64B/row
    __shared__ __align__(16) float Esh4[NC][NG];        // E rows (phase-2 decode)
    __shared__ __align__(16) float Qg[NG][EH][EWP];     // 41472 B

    const int tid = threadIdx.x;
    const int bx = blockIdx.x, by = blockIdx.y, bz = blockIdx.z;

    // ---- E = softmax over G of 100*matrix (dup-pair + row formats) ----
    if (tid < NC) {
        const int c = tid;
        float m[NG];
        float mx = -1e30f;
        #pragma unroll
        for (int g = 0; g < NG; g++) {
            m[g] = 100.0f * matrix[g * NC + c];
            mx = fmaxf(mx, m[g]);
        }
        float s = 0.0f;
        #pragma unroll
        for (int g = 0; g < NG; g++) { m[g] = __expf(m[g] - mx); s += m[g]; }
        const float r = 1.0f / s;
        #pragma unroll
        for (int g = 0; g < NG; g++) {
            const float v = m[g] * r;
            EshDup[c][2 * g]     = v;
            EshDup[c][2 * g + 1] = v;
            Esh4[c][g] = v;
        }
    }
    __syncthreads();

    const int x0 = bx * TW;
    const int y0 = by * TH;
    const float* __restrict__ logit_b = logit + (size_t)bz * NC * HW;

    // ---- Phase 1: softmax+encode; 2 sequential 4-px passes per thread ----
    if (tid < NPAIR) {
        const int r  = tid / 9;
        const int j  = tid - r * 9;
        const int gy = y0 + r - 1;
        const bool rowok = (unsigned)gy < IMH;
        const float2 z2 = make_float2(0.f, 0.f);
        const float4 z4 = make_float4(0.f, 0.f, 0.f, 0.f);

        #pragma unroll
        for (int pass = 0; pass < 2; pass++) {
            const int gxb = x0 - 4 + 8 * j + 4 * pass;
            // 4-aligned group vs 512 image: fully inside or fully outside
            const bool v = rowok && ((unsigned)gxb < IMW);

            float2 a01[NG], a23[NG];
            #pragma unroll
            for (int g = 0; g < NG; g++) { a01[g] = z2; a23[g] = z2; }
            float2 s01 = z2, s23 = z2;

            const float* __restrict__ p = logit_b + (size_t)gy * IMW + gxb;

            #pragma unroll
            for (int c = 0; c < NC; c++) {
                const float4 v4 = v ? __ldg((const float4*)(p + (size_t)c * HW)) : z4;
                const float2 e01 = make_float2(__expf(v4.x), __expf(v4.y));
                const float2 e23 = make_float2(__expf(v4.z), __expf(v4.w));
                s01 = fadd2(s01, e01);
                s23 = fadd2(s23, e23);
                // 4 broadcast LDS.128; each float4 = two (Eg,Eg) FFMA2 operands
                #pragma unroll
                for (int q = 0; q < 4; q++) {
                    const float4 D = *(const float4*)&EshDup[c][4 * q];
                    const float2 pE0 = make_float2(D.x, D.y);   // (E_{2q},   E_{2q})
                    const float2 pE1 = make_float2(D.z, D.w);   // (E_{2q+1}, E_{2q+1})
                    a01[2 * q]     = ffma2(pE0, e01, a01[2 * q]);
                    a23[2 * q]     = ffma2(pE0, e23, a23[2 * q]);
                    a01[2 * q + 1] = ffma2(pE1, e01, a01[2 * q + 1]);
                    a23[2 * q + 1] = ffma2(pE1, e23, a23[2 * q + 1]);
                }
            }
            const float2 r01 = make_float2(__frcp_rn(s01.x), __frcp_rn(s01.y));
            const float2 r23 = make_float2(__frcp_rn(s23.x), __frcp_rn(s23.y));

            #pragma unroll
            for (int g = 0; g < NG; g++) {
                float4 o = z4;
                if (v) {
                    const float2 q01 = fmul2(a01[g], r01);
                    const float2 q23 = fmul2(a23[g], r23);
                    o = make_float4(q01.x, q01.y, q23.x, q23.y);
                }
                *(float4*)&Qg[g][r][8 * j + 4 * pass] = o;
            }
        }
    }
    __syncthreads();

    // ---- Phase 2: 3x3 filter + E-row decode + subtract, 4 px/thread ----
    {
        const int y  = tid >> 4;           // 0..15
        const int xg = (tid & 15) << 2;    // 0,4,..,60
        const int gy = y0 + y;

        const float* __restrict__ fp =
            Fk + (size_t)bz * 9 * HW + (size_t)gy * IMW + (x0 + xg);

        const float2 z2 = make_float2(0.f, 0.f);
        float2 filtT[4][4];                // [pixel][g-pair]: .x even g, .y odd g
        #pragma unroll
        for (int px = 0; px < 4; px++)
            #pragma unroll
            for (int gp = 0; gp < 4; gp++) filtT[px][gp] = z2;

        // dr-outer: stage 3 F taps at a time (register diet for 3 CTAs/SM)
        #pragma unroll
        for (int dr = 0; dr < 3; dr++) {
            const float4 fa = __ldcs((const float4*)(fp + (size_t)(dr * 3 + 0) * HW));
            const float4 fb = __ldcs((const float4*)(fp + (size_t)(dr * 3 + 1) * HW));
            const float4 fc = __ldcs((const float4*)(fp + (size_t)(dr * 3 + 2) * HW));
            #pragma unroll
            for (int g = 0; g < NG; g++) {
                const int gp = g >> 1;
                const float* __restrict__ qrow = &Qg[g][y + dr][xg + 3];
                const float  q0 = qrow[0];
                const float4 qm = *(const float4*)(qrow + 1);
                const float  q5 = qrow[5];
                if (g & 1) {
                    filtT[0][gp].y = fmaf(fa.x, q0,   fmaf(fb.x, qm.x, fmaf(fc.x, qm.y, filtT[0][gp].y)));
                    filtT[1][gp].y = fmaf(fa.y, qm.x, fmaf(fb.y, qm.y, fmaf(fc.y, qm.z, filtT[1][gp].y)));
                    filtT[2][gp].y = fmaf(fa.z, qm.y, fmaf(fb.z, qm.z, fmaf(fc.z, qm.w, filtT[2][gp].y)));
                    filtT[3][gp].y = fmaf(fa.w, qm.z, fmaf(fb.w, qm.w, fmaf(fc.w, q5,   filtT[3][gp].y)));
                } else {
                    filtT[0][gp].x = fmaf(fa.x, q0,   fmaf(fb.x, qm.x, fmaf(fc.x, qm.y, filtT[0][gp].x)));
                    filtT[1][gp].x = fmaf(fa.y, qm.x, fmaf(fb.y, qm.y, fmaf(fc.y, qm.z, filtT[1][gp].x)));
                    filtT[2][gp].x = fmaf(fa.z, qm.y, fmaf(fb.z, qm.z, fmaf(fc.z, qm.w, filtT[2][gp].x)));
                    filtT[3][gp].x = fmaf(fa.w, qm.z, fmaf(fb.w, qm.w, fmaf(fc.w, q5,   filtT[3][gp].x)));
                }
            }
        }

        const float* __restrict__ lp = logit_b + (size_t)gy * IMW + (x0 + xg);
        float* __restrict__       op = out + (size_t)bz * NC * HW
                                           + (size_t)gy * IMW + (x0 + xg);
        #pragma unroll
        for (int c = 0; c < NC; c++) {
            const float4 Ea = *(const float4*)&Esh4[c][0];   // (E0,E1,E2,E3)
            const float4 Eb = *(const float4*)&Esh4[c][4];   // (E4,E5,E6,E7)
            const float2 Ep0 = make_float2(Ea.x, Ea.y);
            const float2 Ep1 = make_float2(Ea.z, Ea.w);
            const float2 Ep2 = make_float2(Eb.x, Eb.y);
            const float2 Ep3 = make_float2(Eb.z, Eb.w);
            float2 a0 = z2, a1 = z2, a2 = z2, a3 = z2;
            a0 = ffma2(Ep0, filtT[0][0], a0);
            a0 = ffma2(Ep1, filtT[0][1], a0);
            a0 = ffma2(Ep2, filtT[0][2], a0);
            a0 = ffma2(Ep3, filtT[0][3], a0);
            a1 = ffma2(Ep0, filtT[1][0], a1);
            a1 = ffma2(Ep1, filtT[1][1], a1);
            a1 = ffma2(Ep2, filtT[1][2], a1);
            a1 = ffma2(Ep3, filtT[1][3], a1);
            a2 = ffma2(Ep0, filtT[2][0], a2);
            a2 = ffma2(Ep1, filtT[2][1], a2);
            a2 = ffma2(Ep2, filtT[2][2], a2);
            a2 = ffma2(Ep3, filtT[2][3], a2);
            a3 = ffma2(Ep0, filtT[3][0], a3);
            a3 = ffma2(Ep1, filtT[3][1], a3);
            a3 = ffma2(Ep2, filtT[3][2], a3);
            a3 = ffma2(Ep3, filtT[3][3], a3);
            const float4 l4 = __ldg((const float4*)(lp + (size_t)c * HW));
            float4 o;
            o.x = l4.x - (a0.x + a0.y);
            o.y = l4.y - (a1.x + a1.y);
            o.z = l4.z - (a2.x + a2.y);
            o.w = l4.w - (a3.x + a3.y);
            __stcs((float4*)(op + (size_t)c * HW), o);
        }
    }
}

extern "C" void kernel_launch(void* const* d_in, const int* in_sizes, int n_in,
                              void* d_out, int out_size) {
    // Bind inputs by element count (robust to ordering):
    //   F: 9437184, logit: 19922944, matrix: 152
    const float* F      = nullptr;
    const float* logit  = nullptr;
    const float* matrix = nullptr;
    for (int i = 0; i < n_in; i++) {
        if (in_sizes[i] == 9437184)       F      = (const float*)d_in[i];
        else if (in_sizes[i] == 19922944) logit  = (const float*)d_in[i];
        else if (in_sizes[i] == 152)      matrix = (const float*)d_in[i];
    }
    float* out = (float*)d_out;

    dim3 grid(IMW / TW, IMH / TH, BATCH);   // (8, 32, 4)
    gacrf_fused_kernel<<<grid, NTHREADS>>>(F, logit, matrix, out);
}

// round 13
// speedup vs baseline: 1.0076x; 1.0076x over previous
#include <cuda_runtime.h>

// GACRF fused: softmax(C=19) -> encode(G=8) -> 3x3 dynamic filter -> decode ->
// logit - result.  Single kernel, tile + 1px halo in smem.
//
// R12: ONE phase-1 pass per thread. All R8..R11 variants pinned at 54-55us with
// every pipe <=38%: the invariant is the barrier-gated critical path, whose
// slowest warp ran TWO sequential softmax passes. Tile is now 56x14 so the
// extended halo region is exactly 16 rows x 16 col-groups = 256 four-pixel
// groups -> every thread runs exactly one pass (crit path 2P+Q -> P+Q).
// Qg smem 41.5 -> 32KB, phase-1 accumulator regs halve (deeper LDG batching).
// Ragged image edges (512 % 56 != 0) handled by guards; OOB threads skip the
// exp loop. Inner loops identical to R11.
//
// Shapes (fixed): b=4, C=19, G=8, H=W=512, K=3.

#define BATCH 4
#define NC 19
#define NG 8
#define IMH 512
#define IMW 512
#define HW (IMH * IMW)

#define TW 56            // output tile width
#define TH 14            // output tile height
#define EH 16            // extended rows  (global y0-1 .. y0+14)
#define EWP 64           // extended cols  (global x0-4 .. x0+59), 16 groups
#define NP2 (TH * (TW / 4))   // 196 phase-2 groups
#define NTHREADS 256

#define GRIDX ((IMW + TW - 1) / TW)   // 10
#define GRIDY ((IMH + TH - 1) / TH)   // 37

// ---- packed f32x2 helpers (per-lane IEEE identical to scalar) ----
__device__ __forceinline__ float2 ffma2(float2 a, float2 b, float2 c) {
    float2 d;
    asm("fma.rn.f32x2 %0, %1, %2, %3;"
        : "=l"(*reinterpret_cast<unsigned long long*>(&d))
        : "l"(*reinterpret_cast<unsigned long long*>(&a)),
          "l"(*reinterpret_cast<unsigned long long*>(&b)),
          "l"(*reinterpret_cast<unsigned long long*>(&c)));
    return d;
}
__device__ __forceinline__ float2 fadd2(float2 a, float2 b) {
    float2 d;
    asm("add.rn.f32x2 %0, %1, %2;"
        : "=l"(*reinterpret_cast<unsigned long long*>(&d))
        : "l"(*reinterpret_cast<unsigned long long*>(&a)),
          "l"(*reinterpret_cast<unsigned long long*>(&b)));
    return d;
}
__device__ __forceinline__ float2 fmul2(float2 a, float2 b) {
    float2 d;
    asm("mul.rn.f32x2 %0, %1, %2;"
        : "=l"(*reinterpret_cast<unsigned long long*>(&d))
        : "l"(*reinterpret_cast<unsigned long long*>(&a)),
          "l"(*reinterpret_cast<unsigned long long*>(&b)));
    return d;
}

__global__ __launch_bounds__(NTHREADS, 3) void gacrf_fused_kernel(
    const float* __restrict__ Fk,     // [b,9,H,W]
    const float* __restrict__ logit,  // [b,C,H,W]
    const float* __restrict__ matrix, // [G,C]
    float* __restrict__ out)          // [b,C,H,W]
{
    __shared__ __align__(16) float EshDup[NC][2 * NG];  // [E0,E0,E1,E1,...]
    __shared__ __align__(16) float Esh4[NC][NG];        // E rows (decode)
    __shared__ __align__(16) float Qg[NG][EH][EWP];     // 32768 B

    const int tid = threadIdx.x;
    const int bx = blockIdx.x, by = blockIdx.y, bz = blockIdx.z;

    // ---- E = softmax over G of 100*matrix (dup-pair + row formats) ----
    if (tid < NC) {
        const int c = tid;
        float m[NG];
        float mx = -1e30f;
        #pragma unroll
        for (int g = 0; g < NG; g++) {
            m[g] = 100.0f * matrix[g * NC + c];
            mx = fmaxf(mx, m[g]);
        }
        float s = 0.0f;
        #pragma unroll
        for (int g = 0; g < NG; g++) { m[g] = __expf(m[g] - mx); s += m[g]; }
        const float r = 1.0f / s;
        #pragma unroll
        for (int g = 0; g < NG; g++) {
            const float v = m[g] * r;
            EshDup[c][2 * g]     = v;
            EshDup[c][2 * g + 1] = v;
            Esh4[c][g] = v;
        }
    }
    __syncthreads();

    const int x0 = bx * TW;
    const int y0 = by * TH;
    const float* __restrict__ logit_b = logit + (size_t)bz * NC * HW;

    // ---- Phase 1: softmax+encode, EXACTLY ONE 4-px group per thread ----
    // ext row r <-> global y0 - 1 + r ; ext col 4j.. <-> global x0 - 4 + 4j
    {
        const int r   = tid >> 4;          // 0..15
        const int j   = tid & 15;          // 0..15
        const int gy  = y0 + r - 1;
        const int gxb = x0 - 4 + 4 * j;
        // 4-aligned group vs 512 image: fully inside or fully outside
        const bool v = ((unsigned)gy < IMH) && ((unsigned)gxb < IMW);

        const float2 z2 = make_float2(0.f, 0.f);
        const float4 z4 = make_float4(0.f, 0.f, 0.f, 0.f);
        float2 a01[NG], a23[NG];
        #pragma unroll
        for (int g = 0; g < NG; g++) { a01[g] = z2; a23[g] = z2; }

        if (v) {
            float2 s01 = z2, s23 = z2;
            const float* __restrict__ p = logit_b + (size_t)gy * IMW + gxb;

            #pragma unroll
            for (int c = 0; c < NC; c++) {
                const float4 v4 = __ldg((const float4*)(p + (size_t)c * HW));
                const float2 e01 = make_float2(__expf(v4.x), __expf(v4.y));
                const float2 e23 = make_float2(__expf(v4.z), __expf(v4.w));
                s01 = fadd2(s01, e01);
                s23 = fadd2(s23, e23);
                // 4 broadcast LDS.128; each float4 = two (Eg,Eg) FFMA2 operands
                #pragma unroll
                for (int q = 0; q < 4; q++) {
                    const float4 D = *(const float4*)&EshDup[c][4 * q];
                    const float2 pE0 = make_float2(D.x, D.y);
                    const float2 pE1 = make_float2(D.z, D.w);
                    a01[2 * q]     = ffma2(pE0, e01, a01[2 * q]);
                    a23[2 * q]     = ffma2(pE0, e23, a23[2 * q]);
                    a01[2 * q + 1] = ffma2(pE1, e01, a01[2 * q + 1]);
                    a23[2 * q + 1] = ffma2(pE1, e23, a23[2 * q + 1]);
                }
            }
            const float2 r01 = make_float2(__frcp_rn(s01.x), __frcp_rn(s01.y));
            const float2 r23 = make_float2(__frcp_rn(s23.x), __frcp_rn(s23.y));
            #pragma unroll
            for (int g = 0; g < NG; g++) {
                a01[g] = fmul2(a01[g], r01);
                a23[g] = fmul2(a23[g], r23);
            }
        }
        #pragma unroll
        for (int g = 0; g < NG; g++)
            *(float4*)&Qg[g][r][4 * j] =
                make_float4(a01[g].x, a01[g].y, a23[g].x, a23[g].y);
    }
    __syncthreads();

    // ---- Phase 2: 3x3 filter + E-row decode + subtract, 196 groups ----
    if (tid < NP2) {
        const int y  = tid / (TW / 4);                 // 0..13
        const int xl = (tid - y * (TW / 4)) * 4;       // 0,4,..,52
        const int gy = y0 + y;
        const int gx = x0 + xl;

        if (gy < IMH && gx < IMW) {                    // gx 4-aligned: full group
            const float* __restrict__ fp =
                Fk + (size_t)bz * 9 * HW + (size_t)gy * IMW + gx;

            const float2 z2 = make_float2(0.f, 0.f);
            float2 filtT[4][4];            // [pixel][g-pair]: .x even g, .y odd g
            #pragma unroll
            for (int px = 0; px < 4; px++)
                #pragma unroll
                for (int gp = 0; gp < 4; gp++) filtT[px][gp] = z2;

            #pragma unroll
            for (int dr = 0; dr < 3; dr++) {
                const float4 fa = __ldcs((const float4*)(fp + (size_t)(dr * 3 + 0) * HW));
                const float4 fb = __ldcs((const float4*)(fp + (size_t)(dr * 3 + 1) * HW));
                const float4 fc = __ldcs((const float4*)(fp + (size_t)(dr * 3 + 2) * HW));
                #pragma unroll
                for (int g = 0; g < NG; g++) {
                    const int gp = g >> 1;
                    const float* __restrict__ qrow = &Qg[g][y + dr][xl + 3];
                    const float  q0 = qrow[0];
                    const float4 qm = *(const float4*)(qrow + 1);
                    const float  q5 = qrow[5];
                    if (g & 1) {
                        filtT[0][gp].y = fmaf(fa.x, q0,   fmaf(fb.x, qm.x, fmaf(fc.x, qm.y, filtT[0][gp].y)));
                        filtT[1][gp].y = fmaf(fa.y, qm.x, fmaf(fb.y, qm.y, fmaf(fc.y, qm.z, filtT[1][gp].y)));
                        filtT[2][gp].y = fmaf(fa.z, qm.y, fmaf(fb.z, qm.z, fmaf(fc.z, qm.w, filtT[2][gp].y)));
                        filtT[3][gp].y = fmaf(fa.w, qm.z, fmaf(fb.w, qm.w, fmaf(fc.w, q5,   filtT[3][gp].y)));
                    } else {
                        filtT[0][gp].x = fmaf(fa.x, q0,   fmaf(fb.x, qm.x, fmaf(fc.x, qm.y, filtT[0][gp].x)));
                        filtT[1][gp].x = fmaf(fa.y, qm.x, fmaf(fb.y, qm.y, fmaf(fc.y, qm.z, filtT[1][gp].x)));
                        filtT[2][gp].x = fmaf(fa.z, qm.y, fmaf(fb.z, qm.z, fmaf(fc.z, qm.w, filtT[2][gp].x)));
                        filtT[3][gp].x = fmaf(fa.w, qm.z, fmaf(fb.w, qm.w, fmaf(fc.w, q5,   filtT[3][gp].x)));
                    }
                }
            }

            const float* __restrict__ lp = logit_b + (size_t)gy * IMW + gx;
            float* __restrict__       op = out + (size_t)bz * NC * HW
                                               + (size_t)gy * IMW + gx;
            #pragma unroll
            for (int c = 0; c < NC; c++) {
                const float4 Ea = *(const float4*)&Esh4[c][0];
                const float4 Eb = *(const float4*)&Esh4[c][4];
                const float2 Ep0 = make_float2(Ea.x, Ea.y);
                const float2 Ep1 = make_float2(Ea.z, Ea.w);
                const float2 Ep2 = make_float2(Eb.x, Eb.y);
                const float2 Ep3 = make_float2(Eb.z, Eb.w);
                float2 a0 = z2, a1 = z2, a2 = z2, a3 = z2;
                a0 = ffma2(Ep0, filtT[0][0], a0);
                a0 = ffma2(Ep1, filtT[0][1], a0);
                a0 = ffma2(Ep2, filtT[0][2], a0);
                a0 = ffma2(Ep3, filtT[0][3], a0);
                a1 = ffma2(Ep0, filtT[1][0], a1);
                a1 = ffma2(Ep1, filtT[1][1], a1);
                a1 = ffma2(Ep2, filtT[1][2], a1);
                a1 = ffma2(Ep3, filtT[1][3], a1);
                a2 = ffma2(Ep0, filtT[2][0], a2);
                a2 = ffma2(Ep1, filtT[2][1], a2);
                a2 = ffma2(Ep2, filtT[2][2], a2);
                a2 = ffma2(Ep3, filtT[2][3], a2);
                a3 = ffma2(Ep0, filtT[3][0], a3);
                a3 = ffma2(Ep1, filtT[3][1], a3);
                a3 = ffma2(Ep2, filtT[3][2], a3);
                a3 = ffma2(Ep3, filtT[3][3], a3);
                const float4 l4 = __ldg((const float4*)(lp + (size_t)c * HW));
                float4 o;
                o.x = l4.x - (a0.x + a0.y);
                o.y = l4.y - (a1.x + a1.y);
                o.z = l4.z - (a2.x + a2.y);
                o.w = l4.w - (a3.x + a3.y);
                __stcs((float4*)(op + (size_t)c * HW), o);
            }
        }
    }
}

extern "C" void kernel_launch(void* const* d_in, const int* in_sizes, int n_in,
                              void* d_out, int out_size) {
    // Bind inputs by element count (robust to ordering):
    //   F: 9437184, logit: 19922944, matrix: 152
    const float* F      = nullptr;
    const float* logit  = nullptr;
    const float* matrix = nullptr;
    for (int i = 0; i < n_in; i++) {
        if (in_sizes[i] == 9437184)       F      = (const float*)d_in[i];
        else if (in_sizes[i] == 19922944) logit  = (const float*)d_in[i];
        else if (in_sizes[i] == 152)      matrix = (const float*)d_in[i];
    }
    float* out = (float*)d_out;

    dim3 grid(GRIDX, GRIDY, BATCH);   // (10, 37, 4) = 1480 CTAs
    gacrf_fused_kernel<<<grid, NTHREADS>>>(F, logit, matrix, out);
}